// round 1
// baseline (speedup 1.0000x reference)
#include <cuda_runtime.h>
#include <math.h>

#define N_NODES 50000
#define N_EDGES 800000
#define N_LAYERS 3
#define DIM 64
#define NGRAPH 512
#define GDIM 128

// ---------------- scratch (static device allocations; no cudaMalloc) -------
__device__ float g_h[2][N_NODES * DIM];   // ping-pong node features
__device__ float g_q[N_NODES * DIM];
__device__ float g_k[N_NODES * DIM];
__device__ float g_v[N_NODES * DIM];
__device__ int   g_deg[N_NODES];
__device__ int   g_rowptr[N_NODES + 1];
__device__ int   g_cursor[N_NODES];
__device__ int   g_elist[N_EDGES];
__device__ float g_gsum[NGRAPH * DIM];
__device__ int   g_gcnt[NGRAPH];

// ---------------- CSR build -------------------------------------------------
__global__ void k_zero() {
    int i = blockIdx.x * blockDim.x + threadIdx.x;
    if (i < N_NODES) g_deg[i] = 0;
    if (i < NGRAPH * DIM) g_gsum[i] = 0.f;
    if (i < NGRAPH) g_gcnt[i] = 0;
}

__global__ void k_count(const int* __restrict__ edst, const int* __restrict__ batch) {
    int i = blockIdx.x * blockDim.x + threadIdx.x;
    if (i < N_EDGES) atomicAdd(&g_deg[edst[i]], 1);
    if (i < N_NODES) atomicAdd(&g_gcnt[batch[i]], 1);
}

__global__ void k_scan() {
    __shared__ int sh[1024];
    int tid = threadIdx.x;
    int carry = 0;
    for (int base = 0; base < N_NODES; base += 1024) {
        int idx = base + tid;
        int v = (idx < N_NODES) ? g_deg[idx] : 0;
        sh[tid] = v;
        __syncthreads();
        for (int off = 1; off < 1024; off <<= 1) {
            int t = (tid >= off) ? sh[tid - off] : 0;
            __syncthreads();
            sh[tid] += t;
            __syncthreads();
        }
        int incl = sh[tid];
        int excl = carry + incl - v;
        if (idx < N_NODES) { g_rowptr[idx] = excl; g_cursor[idx] = excl; }
        int tot = sh[1023];
        __syncthreads();
        carry += tot;
    }
    if (tid == 0) g_rowptr[N_NODES] = carry;
}

__global__ void k_fill(const int* __restrict__ edst) {
    int i = blockIdx.x * blockDim.x + threadIdx.x;
    if (i < N_EDGES) {
        int p = atomicAdd(&g_cursor[edst[i]], 1);
        g_elist[p] = i;
    }
}

// ---------------- fused QKV+skip GEMM: [N,64] @ [64,256] --------------------
// Dynamic smem: W[64][256] (Wq|Wk|Wv|Wskip) + bias[256]
__global__ __launch_bounds__(256)
void k_gemm(const float* __restrict__ hin_ext, int inbuf, int outbuf,
            const float* __restrict__ Wq, const float* __restrict__ Wk,
            const float* __restrict__ Wv, const float* __restrict__ Wsk,
            const float* __restrict__ bq, const float* __restrict__ bk,
            const float* __restrict__ bv, const float* __restrict__ bsk) {
    extern __shared__ float smem[];
    float* Wsm = smem;              // 64*256
    float* bsm = smem + 64 * 256;   // 256
    int tid = threadIdx.x;
    for (int idx = tid; idx < 4096; idx += 256) {
        int kk = idx >> 6, j = idx & 63;
        Wsm[kk * 256 + j]       = Wq[idx];
        Wsm[kk * 256 + 64 + j]  = Wk[idx];
        Wsm[kk * 256 + 128 + j] = Wv[idx];
        Wsm[kk * 256 + 192 + j] = Wsk[idx];
    }
    if (tid < 64) {
        bsm[tid]       = bq[tid];
        bsm[64 + tid]  = bk[tid];
        bsm[128 + tid] = bv[tid];
        bsm[192 + tid] = bsk[tid];
    }
    __syncthreads();

    const float* hin = hin_ext ? hin_ext : (const float*)g_h[inbuf];
    float* hout = g_h[outbuf];

    int warp = tid >> 5, lane = tid & 31;
    int row = blockIdx.x * 8 + warp;
    if (row >= N_NODES) return;

    float xv0 = hin[row * 64 + lane];
    float xv1 = hin[row * 64 + 32 + lane];
    int jb = lane * 8;
    float acc[8];
#pragma unroll
    for (int jj = 0; jj < 8; jj++) acc[jj] = bsm[jb + jj];
#pragma unroll
    for (int kk = 0; kk < 64; kk++) {
        float xk = (kk < 32) ? __shfl_sync(0xffffffffu, xv0, kk)
                             : __shfl_sync(0xffffffffu, xv1, kk - 32);
#pragma unroll
        for (int jj = 0; jj < 8; jj++) acc[jj] += xk * Wsm[kk * 256 + jb + jj];
    }
    int m = jb >> 6, c = jb & 63;
    float* outp;
    if (m == 0)      outp = &g_q[row * 64 + c];
    else if (m == 1) outp = &g_k[row * 64 + c];
    else if (m == 2) outp = &g_v[row * 64 + c];
    else             outp = &hout[row * 64 + c];
    *(float4*)(outp)     = make_float4(acc[0], acc[1], acc[2], acc[3]);
    *(float4*)(outp + 4) = make_float4(acc[4], acc[5], acc[6], acc[7]);
}

// ---------------- per-node attention with online softmax --------------------
// one warp per node; lane handles channels 2*lane, 2*lane+1; head = lane/8
__global__ __launch_bounds__(256)
void k_attn(const int* __restrict__ esrc, const float* __restrict__ ea,
            const float* __restrict__ Wel, const int* __restrict__ batch,
            int iobuf, float* __restrict__ out_nodes, int mode) {
    int gwarp = (blockIdx.x * blockDim.x + threadIdx.x) >> 5;
    int lane = threadIdx.x & 31;
    if (gwarp >= N_NODES) return;
    int i = gwarp;
    int ch0 = 2 * lane;

    float* hio = g_h[iobuf];
    float2 qv = *(const float2*)&g_q[i * 64 + ch0];
    float we0 = Wel[ch0], we1 = Wel[ch0 + 1];
    int beg = g_rowptr[i], end = g_rowptr[i + 1];

    float m = -3.4e38f, d = 0.f, a0 = 0.f, a1 = 0.f;
    for (int e = beg; e < end; e++) {
        int eid = g_elist[e];
        int s = esrc[eid];
        float av = ea[eid];
        float2 kv = *(const float2*)&g_k[s * 64 + ch0];
        float e0 = av * we0, e1 = av * we1;
        float p = qv.x * (kv.x + e0) + qv.y * (kv.y + e1);
        p += __shfl_xor_sync(0xffffffffu, p, 1);
        p += __shfl_xor_sync(0xffffffffu, p, 2);
        p += __shfl_xor_sync(0xffffffffu, p, 4);
        float score = p * 0.25f;  // 1/sqrt(16)
        float mn = fmaxf(m, score);
        float corr = __expf(m - mn);
        float w = __expf(score - mn);
        m = mn;
        d = d * corr + w;
        float2 vv = *(const float2*)&g_v[s * 64 + ch0];
        a0 = a0 * corr + w * (vv.x + e0);
        a1 = a1 * corr + w * (vv.y + e1);
    }
    float inv = 1.f / (d + 1e-16f);
    float o0 = hio[i * 64 + ch0]     + a0 * inv;
    float o1 = hio[i * 64 + ch0 + 1] + a1 * inv;
    if (mode == 0) { o0 = fmaxf(o0, 0.f); o1 = fmaxf(o1, 0.f); }
    hio[i * 64 + ch0]     = o0;
    hio[i * 64 + ch0 + 1] = o1;
    if (mode == 1) {
        out_nodes[i * 64 + ch0]     = o0;
        out_nodes[i * 64 + ch0 + 1] = o1;
        int g = batch[i];
        atomicAdd(&g_gsum[g * 64 + ch0], o0);
        atomicAdd(&g_gsum[g * 64 + ch0 + 1], o1);
    }
}

// ---------------- mean pool + graph MLP -------------------------------------
__global__ __launch_bounds__(128)
void k_mlp(const float* __restrict__ W1, const float* __restrict__ b1,
           const float* __restrict__ W2, const float* __restrict__ b2,
           const float* __restrict__ W3, const float* __restrict__ b3,
           float* __restrict__ out_g) {
    __shared__ float gm[64], h1[64], h2[16];
    int g = blockIdx.x, t = threadIdx.x;
    if (t < 64) {
        float cnt = fmaxf((float)g_gcnt[g], 1.f);
        gm[t] = g_gsum[g * 64 + t] / cnt;
    }
    __syncthreads();
    if (t < 64) {
        float acc = b1[t];
#pragma unroll 8
        for (int k = 0; k < 64; k++) acc += gm[k] * W1[k * 64 + t];
        h1[t] = fmaxf(acc, 0.f);
    }
    __syncthreads();
    if (t < 16) {
        float acc = b2[t];
#pragma unroll 8
        for (int k = 0; k < 64; k++) acc += h1[k] * W2[k * 16 + t];
        h2[t] = fmaxf(acc, 0.f);
    }
    __syncthreads();
    {
        float acc = b3[t];
#pragma unroll
        for (int k = 0; k < 16; k++) acc += h2[k] * W3[k * 128 + t];
        out_g[g * 128 + t] = acc;
    }
}

// ---------------- host ------------------------------------------------------
extern "C" void kernel_launch(void* const* d_in, const int* in_sizes, int n_in,
                              void* d_out, int out_size) {
    const float *x = 0, *ea = 0;
    const int *eidx = 0, *batch = 0;
    const float *Wq = 0, *bq = 0, *Wk = 0, *bk = 0, *Wv = 0, *bv = 0;
    const float *We = 0, *Wsk = 0, *bsk = 0;
    const float *W1 = 0, *b1 = 0, *W2 = 0, *b2 = 0, *W3 = 0, *b3 = 0;
    int n12288 = 0, n192 = 0;
    for (int i = 0; i < n_in; i++) {
        int sz = in_sizes[i];
        const void* p = d_in[i];
        switch (sz) {
            case 3200000: x = (const float*)p; break;
            case 800000:  ea = (const float*)p; break;
            case 1600000: eidx = (const int*)p; break;
            case 50000:   batch = (const int*)p; break;
            case 12288: {
                const float* f = (const float*)p;
                if (n12288 == 0) Wq = f; else if (n12288 == 1) Wk = f;
                else if (n12288 == 2) Wv = f; else Wsk = f;
                n12288++;
            } break;
            case 192: {
                const float* f = (const float*)p;
                if (n192 == 0) bq = f; else if (n192 == 1) bk = f;
                else if (n192 == 2) bv = f; else if (n192 == 3) We = f;
                else bsk = f;
                n192++;
            } break;
            case 4096: W1 = (const float*)p; break;
            case 64:   b1 = (const float*)p; break;
            case 1024: W2 = (const float*)p; break;
            case 16:   b2 = (const float*)p; break;
            case 2048: W3 = (const float*)p; break;
            case 128:  b3 = (const float*)p; break;
        }
    }
    const int* esrc = eidx;
    const int* edst = eidx + N_EDGES;
    float* out_nodes = (float*)d_out;
    float* out_graph = out_nodes + (size_t)N_NODES * DIM;

    const int smem_gemm = (64 * 256 + 256) * sizeof(float);  // 66560 B
    cudaFuncSetAttribute(k_gemm, cudaFuncAttributeMaxDynamicSharedMemorySize, smem_gemm);

    // CSR by destination + graph counts (recomputed every replay; deterministic work)
    k_zero<<<(N_NODES + 255) / 256, 256>>>();
    k_count<<<(N_EDGES + 255) / 256, 256>>>(edst, batch);
    k_scan<<<1, 1024>>>();
    k_fill<<<(N_EDGES + 255) / 256, 256>>>(edst);

    const int gemm_grid = (N_NODES + 7) / 8;
    const int attn_grid = (N_NODES * 32 + 255) / 256;

    // layer 0: input = x, buffers -> g_h[0]
    k_gemm<<<gemm_grid, 256, smem_gemm>>>(x, 0, 0,
        Wq + 0 * 4096, Wk + 0 * 4096, Wv + 0 * 4096, Wsk + 0 * 4096,
        bq + 0 * 64, bk + 0 * 64, bv + 0 * 64, bsk + 0 * 64);
    k_attn<<<attn_grid, 256>>>(esrc, ea, We + 0 * 64, batch, 0, out_nodes, 0);

    // layer 1: g_h[0] -> g_h[1]
    k_gemm<<<gemm_grid, 256, smem_gemm>>>(nullptr, 0, 1,
        Wq + 1 * 4096, Wk + 1 * 4096, Wv + 1 * 4096, Wsk + 1 * 4096,
        bq + 1 * 64, bk + 1 * 64, bv + 1 * 64, bsk + 1 * 64);
    k_attn<<<attn_grid, 256>>>(esrc, ea, We + 1 * 64, batch, 1, out_nodes, 0);

    // layer 2 (last): g_h[1] -> g_h[0]; writes node embeddings + pooling sums
    k_gemm<<<gemm_grid, 256, smem_gemm>>>(nullptr, 1, 0,
        Wq + 2 * 4096, Wk + 2 * 4096, Wv + 2 * 4096, Wsk + 2 * 4096,
        bq + 2 * 64, bk + 2 * 64, bv + 2 * 64, bsk + 2 * 64);
    k_attn<<<attn_grid, 256>>>(esrc, ea, We + 2 * 64, batch, 0, out_nodes, 1);

    // mean pool + MLP head
    k_mlp<<<NGRAPH, 128>>>(W1, b1, W2, b2, W3, b3, out_graph);
}

// round 3
// speedup vs baseline: 2.1782x; 2.1782x over previous
#include <cuda_runtime.h>
#include <math.h>

#define N_NODES 50000
#define N_EDGES 800000
#define DIM 64
#define NGRAPH 512
#define GDIM 128
#define NBLK 196          // ceil(50000/256)

// ---------------- scratch (static device arrays; no cudaMalloc) -------------
__device__ float  g_h[2][N_NODES * DIM];     // ping-pong node features
__device__ float  g_q[N_NODES * DIM];
__device__ float4 g_kv[N_NODES * 32];        // per node: 32 x (k0,k1,v0,v1)
__device__ int    g_deg[N_NODES];
__device__ int    g_rowptr[N_NODES + 1];
__device__ int    g_cursor[N_NODES];
__device__ int2   g_edge[N_EDGES];           // (src, bitcast(edge_attr)) sorted by dst
__device__ int    g_bsum[NBLK];
__device__ int    g_boff[NBLK];
__device__ float  g_gsum[NGRAPH * DIM];
__device__ int    g_gcnt[NGRAPH];

// ---------------- CSR build -------------------------------------------------
__global__ void k_zero() {
    int i = blockIdx.x * blockDim.x + threadIdx.x;
    if (i < N_NODES) g_deg[i] = 0;
    if (i < NGRAPH * DIM) g_gsum[i] = 0.f;
    if (i < NGRAPH) g_gcnt[i] = 0;
}

__global__ void k_count(const int* __restrict__ edst, const int* __restrict__ batch) {
    int i = blockIdx.x * blockDim.x + threadIdx.x;
    if (i < N_EDGES) atomicAdd(&g_deg[edst[i]], 1);
    if (i < N_NODES) atomicAdd(&g_gcnt[batch[i]], 1);
}

// block-level scan of degrees -> local exclusive prefix + block sums
__global__ __launch_bounds__(256) void k_scan1() {
    __shared__ int wsum[8];
    int b = blockIdx.x, t = threadIdx.x;
    int idx = b * 256 + t;
    int v = (idx < N_NODES) ? g_deg[idx] : 0;
    int lane = t & 31, w = t >> 5;
    int s = v;
#pragma unroll
    for (int o = 1; o < 32; o <<= 1) {
        int n = __shfl_up_sync(0xffffffffu, s, o);
        if (lane >= o) s += n;
    }
    if (lane == 31) wsum[w] = s;
    __syncthreads();
    if (w == 0) {
        int ws = (lane < 8) ? wsum[lane] : 0;
#pragma unroll
        for (int o = 1; o < 8; o <<= 1) {
            int n = __shfl_up_sync(0xffffffffu, ws, o);
            if (lane >= o) ws += n;
        }
        if (lane < 8) wsum[lane] = ws;
    }
    __syncthreads();
    int incl = s + (w ? wsum[w - 1] : 0);
    if (idx < N_NODES) g_rowptr[idx] = incl - v;
    if (t == 255) g_bsum[b] = incl;
}

__global__ __launch_bounds__(256) void k_scan2() {
    __shared__ int wsum[8];
    int t = threadIdx.x;
    int v = (t < NBLK) ? g_bsum[t] : 0;
    int lane = t & 31, w = t >> 5;
    int s = v;
#pragma unroll
    for (int o = 1; o < 32; o <<= 1) {
        int n = __shfl_up_sync(0xffffffffu, s, o);
        if (lane >= o) s += n;
    }
    if (lane == 31) wsum[w] = s;
    __syncthreads();
    if (w == 0) {
        int ws = (lane < 8) ? wsum[lane] : 0;
#pragma unroll
        for (int o = 1; o < 8; o <<= 1) {
            int n = __shfl_up_sync(0xffffffffu, ws, o);
            if (lane >= o) ws += n;
        }
        if (lane < 8) wsum[lane] = ws;
    }
    __syncthreads();
    int incl = s + (w ? wsum[w - 1] : 0);
    if (t < NBLK) g_boff[t] = incl - v;
    if (t == NBLK - 1) g_rowptr[N_NODES] = incl;
}

__global__ __launch_bounds__(256) void k_scan3() {
    int idx = blockIdx.x * 256 + threadIdx.x;
    if (idx < N_NODES) {
        int r = g_rowptr[idx] + g_boff[blockIdx.x];
        g_rowptr[idx] = r;
        g_cursor[idx] = r;
    }
}

__global__ void k_fill(const int* __restrict__ esrc, const int* __restrict__ edst,
                       const float* __restrict__ ea) {
    int i = blockIdx.x * blockDim.x + threadIdx.x;
    if (i < N_EDGES) {
        int p = atomicAdd(&g_cursor[edst[i]], 1);
        g_edge[p] = make_int2(esrc[i], __float_as_int(ea[i]));
    }
}

// ---------------- fused QKV+skip GEMM: [N,64] @ [64,256], 4 rows/warp -------
__global__ __launch_bounds__(256)
void k_gemm(const float* __restrict__ hin_ext, int inbuf, int outbuf,
            const float* __restrict__ Wq, const float* __restrict__ Wk,
            const float* __restrict__ Wv, const float* __restrict__ Wsk,
            const float* __restrict__ bq, const float* __restrict__ bk,
            const float* __restrict__ bv, const float* __restrict__ bsk) {
    extern __shared__ float smem[];
    float* Wsm = smem;              // 64*256
    float* bsm = smem + 64 * 256;   // 256
    int tid = threadIdx.x;
    for (int idx = tid; idx < 4096; idx += 256) {
        int kk = idx >> 6, j = idx & 63;
        Wsm[kk * 256 + j]       = Wq[idx];
        Wsm[kk * 256 + 64 + j]  = Wk[idx];
        Wsm[kk * 256 + 128 + j] = Wv[idx];
        Wsm[kk * 256 + 192 + j] = Wsk[idx];
    }
    if (tid < 64) {
        bsm[tid]       = bq[tid];
        bsm[64 + tid]  = bk[tid];
        bsm[128 + tid] = bv[tid];
        bsm[192 + tid] = bsk[tid];
    }
    __syncthreads();

    const float* hin = hin_ext ? hin_ext : (const float*)g_h[inbuf];
    float* hout = g_h[outbuf];

    int warp = tid >> 5, lane = tid & 31;
    int rbase = blockIdx.x * 32 + warp * 4;
    if (rbase >= N_NODES) return;

    float x0[4], x1[4];
#pragma unroll
    for (int r = 0; r < 4; r++) {
        int row = min(rbase + r, N_NODES - 1);
        x0[r] = hin[row * 64 + lane];
        x1[r] = hin[row * 64 + 32 + lane];
    }

    int jb = lane * 8;
    float acc[4][8];
#pragma unroll
    for (int r = 0; r < 4; r++)
#pragma unroll
        for (int jj = 0; jj < 8; jj++) acc[r][jj] = bsm[jb + jj];

#pragma unroll
    for (int kk = 0; kk < 32; kk++) {
        float4 wa = *(const float4*)&Wsm[kk * 256 + jb];
        float4 wb = *(const float4*)&Wsm[kk * 256 + jb + 4];
#pragma unroll
        for (int r = 0; r < 4; r++) {
            float xk = __shfl_sync(0xffffffffu, x0[r], kk);
            acc[r][0] += xk * wa.x; acc[r][1] += xk * wa.y;
            acc[r][2] += xk * wa.z; acc[r][3] += xk * wa.w;
            acc[r][4] += xk * wb.x; acc[r][5] += xk * wb.y;
            acc[r][6] += xk * wb.z; acc[r][7] += xk * wb.w;
        }
    }
#pragma unroll
    for (int kk = 0; kk < 32; kk++) {
        float4 wa = *(const float4*)&Wsm[(kk + 32) * 256 + jb];
        float4 wb = *(const float4*)&Wsm[(kk + 32) * 256 + jb + 4];
#pragma unroll
        for (int r = 0; r < 4; r++) {
            float xk = __shfl_sync(0xffffffffu, x1[r], kk);
            acc[r][0] += xk * wa.x; acc[r][1] += xk * wa.y;
            acc[r][2] += xk * wa.z; acc[r][3] += xk * wa.w;
            acc[r][4] += xk * wb.x; acc[r][5] += xk * wb.y;
            acc[r][6] += xk * wb.z; acc[r][7] += xk * wb.w;
        }
    }

    int m = jb >> 6, c = jb & 63;
    float* kvf = (float*)g_kv;
#pragma unroll
    for (int r = 0; r < 4; r++) {
        int row = rbase + r;
        if (row >= N_NODES) break;
        if (m == 0) {
            *(float4*)&g_q[row * 64 + c]     = make_float4(acc[r][0], acc[r][1], acc[r][2], acc[r][3]);
            *(float4*)&g_q[row * 64 + c + 4] = make_float4(acc[r][4], acc[r][5], acc[r][6], acc[r][7]);
        } else if (m == 3) {
            *(float4*)&hout[row * 64 + c]     = make_float4(acc[r][0], acc[r][1], acc[r][2], acc[r][3]);
            *(float4*)&hout[row * 64 + c + 4] = make_float4(acc[r][4], acc[r][5], acc[r][6], acc[r][7]);
        } else {
            // interleaved kv: pair p = ch/2 lives at kvf[row*128 + p*4 + (k:0 / v:2)]
            int base = row * 128 + c * 2 + ((m == 2) ? 2 : 0);
#pragma unroll
            for (int j = 0; j < 4; j++)
                *(float2*)&kvf[base + j * 4] = make_float2(acc[r][2 * j], acc[r][2 * j + 1]);
        }
    }
}

// ---------------- per-node attention, online softmax, 4-edge ILP ------------
#define PROC(KV, AV, MM, DD, AA0, AA1)                                        \
    {                                                                         \
        float e0 = (AV) * we0, e1 = (AV) * we1;                               \
        float p = qv.x * ((KV).x + e0) + qv.y * ((KV).y + e1);                \
        p += __shfl_xor_sync(0xffffffffu, p, 1);                              \
        p += __shfl_xor_sync(0xffffffffu, p, 2);                              \
        p += __shfl_xor_sync(0xffffffffu, p, 4);                              \
        float sc = p * 0.25f;                                                 \
        float mn = fmaxf(MM, sc);                                             \
        float corr = __expf(MM - mn);                                         \
        float w = __expf(sc - mn);                                            \
        MM = mn;                                                              \
        DD = DD * corr + w;                                                   \
        AA0 = AA0 * corr + w * ((KV).z + e0);                                 \
        AA1 = AA1 * corr + w * ((KV).w + e1);                                 \
    }

__global__ __launch_bounds__(256)
void k_attn(const float* __restrict__ Wel, const int* __restrict__ batch,
            int iobuf, float* __restrict__ out_nodes, int mode) {
    int node = (blockIdx.x * 256 + threadIdx.x) >> 5;
    int lane = threadIdx.x & 31;
    if (node >= N_NODES) return;

    float* hio = g_h[iobuf];
    float2 qv = *(const float2*)&g_q[node * 64 + lane * 2];
    float we0 = Wel[lane * 2], we1 = Wel[lane * 2 + 1];
    int beg = g_rowptr[node], end = g_rowptr[node + 1];

    float m0 = -3.4e38f, m1 = m0, m2 = m0, m3 = m0;
    float d0 = 0.f, d1 = 0.f, d2 = 0.f, d3 = 0.f;
    float a00 = 0.f, a01 = 0.f, a10 = 0.f, a11 = 0.f;
    float a20 = 0.f, a21 = 0.f, a30 = 0.f, a31 = 0.f;

    int e = beg;
    for (; e + 4 <= end; e += 4) {
        int2 E0 = g_edge[e], E1 = g_edge[e + 1], E2 = g_edge[e + 2], E3 = g_edge[e + 3];
        float4 kv0 = g_kv[E0.x * 32 + lane];
        float4 kv1 = g_kv[E1.x * 32 + lane];
        float4 kv2 = g_kv[E2.x * 32 + lane];
        float4 kv3 = g_kv[E3.x * 32 + lane];
        float av0 = __int_as_float(E0.y), av1 = __int_as_float(E1.y);
        float av2 = __int_as_float(E2.y), av3 = __int_as_float(E3.y);
        PROC(kv0, av0, m0, d0, a00, a01);
        PROC(kv1, av1, m1, d1, a10, a11);
        PROC(kv2, av2, m2, d2, a20, a21);
        PROC(kv3, av3, m3, d3, a30, a31);
    }
    for (; e < end; e++) {
        int2 E0 = g_edge[e];
        float4 kv0 = g_kv[E0.x * 32 + lane];
        float av0 = __int_as_float(E0.y);
        PROC(kv0, av0, m0, d0, a00, a01);
    }

    // merge 4 online-softmax accumulator sets
    float M = fmaxf(fmaxf(m0, m1), fmaxf(m2, m3));
    float w0 = __expf(m0 - M), w1 = __expf(m1 - M);
    float w2 = __expf(m2 - M), w3 = __expf(m3 - M);
    float d = d0 * w0 + d1 * w1 + d2 * w2 + d3 * w3;
    float A0 = a00 * w0 + a10 * w1 + a20 * w2 + a30 * w3;
    float A1 = a01 * w0 + a11 * w1 + a21 * w2 + a31 * w3;

    float inv = 1.f / (d + 1e-16f);
    float o0 = hio[node * 64 + lane * 2]     + A0 * inv;
    float o1 = hio[node * 64 + lane * 2 + 1] + A1 * inv;
    if (mode == 0) { o0 = fmaxf(o0, 0.f); o1 = fmaxf(o1, 0.f); }
    hio[node * 64 + lane * 2]     = o0;
    hio[node * 64 + lane * 2 + 1] = o1;
    if (mode == 1) {
        out_nodes[node * 64 + lane * 2]     = o0;
        out_nodes[node * 64 + lane * 2 + 1] = o1;
        int g = batch[node];
        atomicAdd(&g_gsum[g * 64 + lane * 2], o0);
        atomicAdd(&g_gsum[g * 64 + lane * 2 + 1], o1);
    }
}

// ---------------- mean pool + graph MLP -------------------------------------
__global__ __launch_bounds__(128)
void k_mlp(const float* __restrict__ W1, const float* __restrict__ b1,
           const float* __restrict__ W2, const float* __restrict__ b2,
           const float* __restrict__ W3, const float* __restrict__ b3,
           float* __restrict__ out_g) {
    __shared__ float gm[64], h1[64], h2[16];
    int g = blockIdx.x, t = threadIdx.x;
    if (t < 64) {
        float cnt = fmaxf((float)g_gcnt[g], 1.f);
        gm[t] = g_gsum[g * 64 + t] / cnt;
    }
    __syncthreads();
    if (t < 64) {
        float acc = b1[t];
#pragma unroll 8
        for (int k = 0; k < 64; k++) acc += gm[k] * W1[k * 64 + t];
        h1[t] = fmaxf(acc, 0.f);
    }
    __syncthreads();
    if (t < 16) {
        float acc = b2[t];
#pragma unroll 8
        for (int k = 0; k < 64; k++) acc += h1[k] * W2[k * 16 + t];
        h2[t] = fmaxf(acc, 0.f);
    }
    __syncthreads();
    {
        float acc = b3[t];
#pragma unroll
        for (int k = 0; k < 16; k++) acc += h2[k] * W3[k * 128 + t];
        out_g[g * 128 + t] = acc;
    }
}

// ---------------- host ------------------------------------------------------
extern "C" void kernel_launch(void* const* d_in, const int* in_sizes, int n_in,
                              void* d_out, int out_size) {
    const float *x = 0, *ea = 0;
    const int *eidx = 0, *batch = 0;
    const float *Wq = 0, *bq = 0, *Wk = 0, *bk = 0, *Wv = 0, *bv = 0;
    const float *We = 0, *Wsk = 0, *bsk = 0;
    const float *W1 = 0, *b1 = 0, *W2 = 0, *b2 = 0, *W3 = 0, *b3 = 0;
    int n12288 = 0, n192 = 0;
    for (int i = 0; i < n_in; i++) {
        int sz = in_sizes[i];
        const void* p = d_in[i];
        switch (sz) {
            case 3200000: x = (const float*)p; break;
            case 800000:  ea = (const float*)p; break;
            case 1600000: eidx = (const int*)p; break;
            case 50000:   batch = (const int*)p; break;
            case 12288: {
                const float* f = (const float*)p;
                if (n12288 == 0) Wq = f; else if (n12288 == 1) Wk = f;
                else if (n12288 == 2) Wv = f; else Wsk = f;
                n12288++;
            } break;
            case 192: {
                const float* f = (const float*)p;
                if (n192 == 0) bq = f; else if (n192 == 1) bk = f;
                else if (n192 == 2) bv = f; else if (n192 == 3) We = f;
                else bsk = f;
                n192++;
            } break;
            case 4096: W1 = (const float*)p; break;
            case 64:   b1 = (const float*)p; break;
            case 1024: W2 = (const float*)p; break;
            case 16:   b2 = (const float*)p; break;
            case 2048: W3 = (const float*)p; break;
            case 128:  b3 = (const float*)p; break;
        }
    }
    const int* esrc = eidx;
    const int* edst = eidx + N_EDGES;
    float* out_nodes = (float*)d_out;
    float* out_graph = out_nodes + (size_t)N_NODES * DIM;

    const int smem_gemm = (64 * 256 + 256) * sizeof(float);  // 66560 B
    cudaFuncSetAttribute(k_gemm, cudaFuncAttributeMaxDynamicSharedMemorySize, smem_gemm);

    // CSR by destination + graph counts
    k_zero<<<(N_NODES + 255) / 256, 256>>>();
    k_count<<<(N_EDGES + 255) / 256, 256>>>(edst, batch);
    k_scan1<<<NBLK, 256>>>();
    k_scan2<<<1, 256>>>();
    k_scan3<<<NBLK, 256>>>();
    k_fill<<<(N_EDGES + 255) / 256, 256>>>(esrc, edst, ea);

    const int gemm_grid = (N_NODES + 31) / 32;
    const int attn_grid = (N_NODES * 32 + 255) / 256;

    // layer 0: input = x -> skip in g_h[0]
    k_gemm<<<gemm_grid, 256, smem_gemm>>>(x, 0, 0,
        Wq + 0 * 4096, Wk + 0 * 4096, Wv + 0 * 4096, Wsk + 0 * 4096,
        bq + 0 * 64, bk + 0 * 64, bv + 0 * 64, bsk + 0 * 64);
    k_attn<<<attn_grid, 256>>>(We + 0 * 64, batch, 0, out_nodes, 0);

    // layer 1: g_h[0] -> g_h[1]
    k_gemm<<<gemm_grid, 256, smem_gemm>>>(nullptr, 0, 1,
        Wq + 1 * 4096, Wk + 1 * 4096, Wv + 1 * 4096, Wsk + 1 * 4096,
        bq + 1 * 64, bk + 1 * 64, bv + 1 * 64, bsk + 1 * 64);
    k_attn<<<attn_grid, 256>>>(We + 1 * 64, batch, 1, out_nodes, 0);

    // layer 2 (last): g_h[1] -> g_h[0]; writes node embeddings + pooling sums
    k_gemm<<<gemm_grid, 256, smem_gemm>>>(nullptr, 1, 0,
        Wq + 2 * 4096, Wk + 2 * 4096, Wv + 2 * 4096, Wsk + 2 * 4096,
        bq + 2 * 64, bk + 2 * 64, bv + 2 * 64, bsk + 2 * 64);
    k_attn<<<attn_grid, 256>>>(We + 2 * 64, batch, 0, out_nodes, 1);

    // mean pool + MLP head
    k_mlp<<<NGRAPH, 128>>>(W1, b1, W2, b2, W3, b3, out_graph);
}